// round 15
// baseline (speedup 1.0000x reference)
#include <cuda_runtime.h>
#include <cuda_fp16.h>
#include <cstdint>

#define TDIM   8
#define NTOK   8192
#define DLAT   1024
#define DSYM   256
#define NCODE  512

// ---------------- scratch --------------------------------------------------
static __device__ int    g_used[TDIM];
static __device__ float  g_scores[NTOK * NCODE];
static __device__ float  g_cbn[NCODE];
// half hi/lo buffers
static __device__ __half g_bcH[NTOK * 2 * DLAT],  g_bcL[NTOK * 2 * DLAT];
static __device__ __half g_zcH[NTOK * (DLAT + DSYM)], g_zcL[NTOK * (DLAT + DSYM)];
static __device__ __half g_rwH[NTOK * DSYM],      g_rwL[NTOK * DSYM];
static __device__ __half g_hH[NTOK * DLAT];
static __device__ __half g_WreadH[DLAT * 2 * DLAT], g_WreadL[DLAT * 2 * DLAT];
static __device__ __half g_WsymH[DSYM * DLAT],    g_WsymL[DSYM * DLAT];
static __device__ __half g_Wc1H[DLAT * (DLAT + DSYM)], g_Wc1L[DLAT * (DLAT + DSYM)];
static __device__ __half g_Wc2H[DLAT * DLAT],     g_Wc2L[DLAT * DLAT];
static __device__ __half g_cbH[NCODE * DSYM],     g_cbL[NCODE * DSYM];

static __device__ __forceinline__ void split_h(float v, __half& h, __half& l) {
    h = __float2half_rn(v);
    l = __float2half_rn(v - __half2float(h));
}

// ---------------- small kernels --------------------------------------------
// codebook norms + codebook hi/lo convert + g_used init (one warp per code)
__global__ void k_cbprep(const float* __restrict__ cb) {
    int warp = (blockIdx.x * blockDim.x + threadIdx.x) >> 5;
    int lane = threadIdx.x & 31;
    if (warp >= NCODE) return;
    if (warp == 0 && lane < TDIM) g_used[lane] = 0;
    const float* row = cb + (size_t)warp * DSYM;
    float s = 0.f;
#pragma unroll
    for (int i = 0; i < 8; i++) {
        float v = row[lane + 32 * i];
        s += v * v;
        __half h, l; split_h(v, h, l);
        g_cbH[warp * DSYM + lane + 32 * i] = h;
        g_cbL[warp * DSYM + lane + 32 * i] = l;
    }
#pragma unroll
    for (int o = 16; o; o >>= 1) s += __shfl_xor_sync(0xffffffffu, s, o);
    if (lane == 0) g_cbn[warp] = s;
}

// fused: per-token top-bus argmax + [token | gathered bus] hi/lo build
__global__ void k_route(const float* __restrict__ syms,
                        const float* __restrict__ Wq,
                        const float* __restrict__ token,
                        const float* __restrict__ outs) {
    int warp = (blockIdx.x * blockDim.x + threadIdx.x) >> 5;
    int lane = threadIdx.x & 31;
    if (warp >= NTOK) return;
    float wq[8];
#pragma unroll
    for (int i = 0; i < 8; i++) wq[i] = Wq[lane + 32 * i];
    float best = -3.0e38f;
    int bt = 0;
    for (int t = 0; t < TDIM; t++) {
        const float* row = syms + ((size_t)t * NTOK + warp) * DSYM;
        float s = 0.f;
#pragma unroll
        for (int i = 0; i < 8; i++) s += row[lane + 32 * i] * wq[i];
#pragma unroll
        for (int o = 16; o; o >>= 1) s += __shfl_xor_sync(0xffffffffu, s, o);
        if (s > best) { best = s; bt = t; }   // s identical across lanes -> bt uniform
    }
    if (lane == 0) g_used[bt] = 1;

    const float* srcs[2] = { token + (size_t)warp * DLAT,
                             outs + ((size_t)bt * NTOK + warp) * DLAT };
    size_t obase = (size_t)warp * 2048;
#pragma unroll
    for (int half = 0; half < 2; half++) {
        const float4* src = (const float4*)srcs[half];
        size_t o = obase + half * 1024;
#pragma unroll
        for (int it = 0; it < 4; it++) {
            int e = (it * 32 + lane) * 2;          // float4-pair index
            float4 v0 = src[e];
            float4 v1 = src[e + 1];
            __half h[8], l[8];
            split_h(v0.x, h[0], l[0]); split_h(v0.y, h[1], l[1]);
            split_h(v0.z, h[2], l[2]); split_h(v0.w, h[3], l[3]);
            split_h(v1.x, h[4], l[4]); split_h(v1.y, h[5], l[5]);
            split_h(v1.z, h[6], l[6]); split_h(v1.w, h[7], l[7]);
            __half2 hp[4] = { __halves2half2(h[0], h[1]), __halves2half2(h[2], h[3]),
                              __halves2half2(h[4], h[5]), __halves2half2(h[6], h[7]) };
            __half2 lp[4] = { __halves2half2(l[0], l[1]), __halves2half2(l[2], l[3]),
                              __halves2half2(l[4], l[5]), __halves2half2(l[6], l[7]) };
            *(uint4*)(g_bcH + o + e * 4) = *(uint4*)hp;
            *(uint4*)(g_bcL + o + e * 4) = *(uint4*)lp;
        }
    }
}

// transpose+convert: W[K,N] fp32 -> H/L [N,K] half
__global__ void k_cvt_wt(const float* __restrict__ W, __half* __restrict__ H,
                         __half* __restrict__ L, int K, int N) {
    __shared__ float t[32][33];
    int n0 = blockIdx.x * 32, k0 = blockIdx.y * 32;
    int tx = threadIdx.x, ty = threadIdx.y;    // (32, 8)
#pragma unroll
    for (int i = 0; i < 4; i++)
        t[ty + 8 * i][tx] = W[(size_t)(k0 + ty + 8 * i) * N + n0 + tx];
    __syncthreads();
#pragma unroll
    for (int i = 0; i < 4; i++) {
        float v = t[tx][ty + 8 * i];
        __half h, l; split_h(v, h, l);
        size_t o = (size_t)(n0 + ty + 8 * i) * K + k0 + tx;
        H[o] = h; L[o] = l;
    }
}

// VQ argmin + gathers: fp32 quant out + hi halves into zc cols 1024..1279
__global__ void k_vq(const float* __restrict__ cb,
                     float* __restrict__ quant_out,
                     float* __restrict__ idx_out) {
    int warp = (blockIdx.x * blockDim.x + threadIdx.x) >> 5;
    int lane = threadIdx.x & 31;
    if (warp >= NTOK) return;
    const float* srow = g_scores + (size_t)warp * NCODE;
    float best = 3.0e38f;
    int bi = 0x7fffffff;
    for (int c = lane; c < NCODE; c += 32) {
        float d = g_cbn[c] - 2.f * srow[c];
        if (d < best) { best = d; bi = c; }
    }
#pragma unroll
    for (int o = 16; o; o >>= 1) {
        float ov = __shfl_xor_sync(0xffffffffu, best, o);
        int   oi = __shfl_xor_sync(0xffffffffu, bi, o);
        if (ov < best || (ov == best && oi < bi)) { best = ov; bi = oi; }
    }
    const float4* q = (const float4*)(cb + (size_t)bi * DSYM);
    float4* dst = (float4*)(quant_out + (size_t)warp * DSYM);
#pragma unroll
    for (int i = lane; i < DSYM / 4; i += 32) dst[i] = q[i];
    const float4* qh = (const float4*)(g_cbH + (size_t)bi * DSYM);
    float4* dH = (float4*)(g_zcH + (size_t)warp * 1280 + 1024);
#pragma unroll
    for (int i = lane; i < DSYM / 8; i += 32) dH[i] = qh[i];
    if (lane == 0) idx_out[warp] = (float)bi;
}

__global__ void k_mask(float* __restrict__ mask_out) {
    int t = threadIdx.x;
    if (t < TDIM) mask_out[t] = (g_used[t] == 0) ? 1.f : 0.f;
}

// ---------------- fp16 split tensor GEMM: cp.async + ldmatrix ---------------
// C[M,N] = A[M,K] @ B^T (B stored [N,K]).
// NT=3: D = AhBh + AhBl + AlBh;  NT=2: D = AhBh + AhBl (skip Al)
// CTA 128x128, BK=32, 4 warps (2x2) @ 64x64, 2-stage cp.async,
// ONE sync per k-tile, 64KB smem -> 2 CTAs/SM.   (R11-proven config)
#define STG_B 32768
#define TC_SMEM (2 * STG_B)           // 65536
#define TCTHR 128

#define MMA16816(d, a, b)                                             \
    asm volatile(                                                     \
        "mma.sync.aligned.m16n8k16.row.col.f32.f16.f16.f32 "          \
        "{%0,%1,%2,%3},{%4,%5,%6,%7},{%8,%9},{%0,%1,%2,%3};"          \
        : "+f"(d[0]), "+f"(d[1]), "+f"(d[2]), "+f"(d[3])              \
        : "r"(a[0]), "r"(a[1]), "r"(a[2]), "r"(a[3]),                 \
          "r"(b[0]), "r"(b[1]))

static __device__ __forceinline__ uint32_t smem_u32(const void* p) {
    uint32_t a;
    asm("{ .reg .u64 t; cvta.to.shared.u64 t, %1; cvt.u32.u64 %0, t; }"
        : "=r"(a) : "l"(p));
    return a;
}
static __device__ __forceinline__ void cp16(uint32_t dst, const void* src) {
    asm volatile("cp.async.cg.shared.global [%0], [%1], 16;"
                 :: "r"(dst), "l"(src) : "memory");
}
static __device__ __forceinline__ void ldm4(uint32_t& r0, uint32_t& r1,
                                            uint32_t& r2, uint32_t& r3, uint32_t a) {
    asm volatile("ldmatrix.sync.aligned.m8n8.x4.shared.b16 {%0,%1,%2,%3}, [%4];"
                 : "=r"(r0), "=r"(r1), "=r"(r2), "=r"(r3) : "r"(a));
}

template <int NT>
__global__ __launch_bounds__(TCTHR, 2)
void k_tc(const __half* __restrict__ Ah, const __half* __restrict__ Al, int lda,
          const __half* __restrict__ Bh, const __half* __restrict__ Bl,
          const float* __restrict__ bias, const float* __restrict__ res, int relu,
          float* __restrict__ C, __half* __restrict__ Ch, __half* __restrict__ Cl,
          int ldch, int N, int K)
{
    extern __shared__ char sm[];
    const uint32_t sb = smem_u32(sm);
    const int tid = threadIdx.x;
    const int wid = tid >> 5, lane = tid & 31;
    const int wm = wid & 1, wn = wid >> 1;       // warp grid 2(m) x 2(n)
    const int g = lane >> 2, t4 = lane & 3;
    const int bm = blockIdx.y * 128, bn = blockIdx.x * 128;

    int cr[4], cc[4];
#pragma unroll
    for (int l = 0; l < 4; l++) {
        int c = tid + l * TCTHR;
        cr[l] = c >> 2;
        cc[l] = c & 3;
    }

    auto issue_stage = [&](int t) {
        const int kt = t * 32;
        const uint32_t s0 = sb + (t & 1) * STG_B;
#pragma unroll
        for (int l = 0; l < 4; l++) {
            int r = cr[l], ch = cc[l];
            uint32_t d = s0 + r * 64 + ((ch ^ ((r >> 1) & 3)) << 4);
            size_t ga = (size_t)(bm + r) * lda + kt + ch * 8;
            cp16(d, Ah + ga);
            if (NT == 3) cp16(d + 8192, Al + ga);
            size_t gb = (size_t)(bn + r) * K + kt + ch * 8;
            cp16(d + 16384,  Bh + gb);
            cp16(d + 24576,  Bl + gb);
        }
        asm volatile("cp.async.commit_group;" ::: "memory");
    };

    const int amb = (lane & 7) + 8 * ((lane >> 3) & 1);
    const int akl = (lane >> 4) & 1;
    const int swa = (amb >> 1) & 3;
    const int bnb = (lane & 7) + 8 * ((lane >> 4) & 1);
    const int bkl = (lane >> 3) & 1;
    const int swb = (bnb >> 1) & 3;

    float acc[4][8][4] = {};
    const int T = K / 32;

    issue_stage(0);

    for (int t = 0; t < T; t++) {
        asm volatile("cp.async.wait_group 0;" ::: "memory");
        __syncthreads();
        // Buffer (t+1)&1 == (t-1)&1 already consumed: no extra barrier.
        if (t + 1 < T) issue_stage(t + 1);

        const uint32_t s0 = sb + (t & 1) * STG_B;
        const uint32_t aH = s0, aL = s0 + 8192;
        const uint32_t bH = s0 + 16384, bL = s0 + 24576;
#pragma unroll
        for (int s = 0; s < 2; s++) {
            uint32_t bh[8][2], bl[8][2];
#pragma unroll
            for (int jp = 0; jp < 4; jp++) {
                uint32_t off = (uint32_t)(wn * 64 + jp * 16 + bnb) * 64
                             + (((s * 2 + bkl) ^ swb) << 4);
                ldm4(bh[2 * jp][0], bh[2 * jp][1], bh[2 * jp + 1][0], bh[2 * jp + 1][1],
                     bH + off);
                ldm4(bl[2 * jp][0], bl[2 * jp][1], bl[2 * jp + 1][0], bl[2 * jp + 1][1],
                     bL + off);
            }
#pragma unroll
            for (int i = 0; i < 4; i++) {
                uint32_t off = (uint32_t)(wm * 64 + i * 16 + amb) * 64
                             + (((s * 2 + akl) ^ swa) << 4);
                uint32_t ah[4], al[4];
                ldm4(ah[0], ah[1], ah[2], ah[3], aH + off);
                if (NT == 3) ldm4(al[0], al[1], al[2], al[3], aL + off);
#pragma unroll
                for (int j = 0; j < 8; j++) {
                    MMA16816(acc[i][j], ah, bh[j]);
                    MMA16816(acc[i][j], ah, bl[j]);
                    if (NT == 3) MMA16816(acc[i][j], al, bh[j]);
                }
            }
        }
    }

    // ---- epilogue ----
#pragma unroll
    for (int i = 0; i < 4; i++) {
        int row0 = bm + wm * 64 + i * 16 + g;
#pragma unroll
        for (int j = 0; j < 8; j++) {
            int col = bn + wn * 64 + j * 8 + 2 * t4;
            float2 v0 = make_float2(acc[i][j][0], acc[i][j][1]);
            float2 v1 = make_float2(acc[i][j][2], acc[i][j][3]);
            if (bias) {
                float2 bv = *(const float2*)(bias + col);
                v0.x += bv.x; v0.y += bv.y;
                v1.x += bv.x; v1.y += bv.y;
            }
            if (relu) {
                v0.x = fmaxf(v0.x, 0.f); v0.y = fmaxf(v0.y, 0.f);
                v1.x = fmaxf(v1.x, 0.f); v1.y = fmaxf(v1.y, 0.f);
            }
            size_t o0 = (size_t)row0 * N + col;
            size_t o1 = (size_t)(row0 + 8) * N + col;
            if (res) {
                float2 r0 = *(const float2*)(res + o0);
                float2 r1 = *(const float2*)(res + o1);
                v0.x += r0.x; v0.y += r0.y;
                v1.x += r1.x; v1.y += r1.y;
            }
            if (C) {
                *(float2*)(C + o0) = v0;
                *(float2*)(C + o1) = v1;
            }
            if (Ch) {
                size_t p0 = (size_t)row0 * ldch + col;
                size_t p1 = (size_t)(row0 + 8) * ldch + col;
                __half h0 = __float2half_rn(v0.x), h1 = __float2half_rn(v0.y);
                __half h2 = __float2half_rn(v1.x), h3 = __float2half_rn(v1.y);
                *(__half2*)(Ch + p0) = __halves2half2(h0, h1);
                *(__half2*)(Ch + p1) = __halves2half2(h2, h3);
                if (Cl) {
                    __half l0 = __float2half_rn(v0.x - __half2float(h0));
                    __half l1 = __float2half_rn(v0.y - __half2float(h1));
                    __half l2 = __float2half_rn(v1.x - __half2float(h2));
                    __half l3 = __float2half_rn(v1.y - __half2float(h3));
                    *(__half2*)(Cl + p0) = __halves2half2(l0, l1);
                    *(__half2*)(Cl + p1) = __halves2half2(l2, l3);
                }
            }
        }
    }
}

// ---------------- launch ----------------------------------------------------
extern "C" void kernel_launch(void* const* d_in, const int* in_sizes, int n_in,
                              void* d_out, int out_size)
{
    const float* token = (const float*)d_in[0];
    const float* syms  = (const float*)d_in[1];
    const float* outs  = (const float*)d_in[3];
    const float* Wq    = (const float*)d_in[5];
    const float* Wread = (const float*)d_in[7];
    const float* bread = (const float*)d_in[8];
    const float* Wsym  = (const float*)d_in[9];
    const float* bsym  = (const float*)d_in[10];
    const float* Wc1   = (const float*)d_in[11];
    const float* bc1   = (const float*)d_in[12];
    const float* Wc2   = (const float*)d_in[13];
    const float* bc2   = (const float*)d_in[14];
    const float* cb    = (const float*)d_in[15];

    float* out        = (float*)d_out;
    float* out_node   = out;
    float* out_quant  = out + (size_t)NTOK * DLAT;
    float* out_idx    = out_quant + (size_t)NTOK * DSYM;
    float* out_mask   = out_idx + NTOK;

#define SYM_PTR(T, sym) ([]{ void* p; cudaGetSymbolAddress(&p, sym); return (T*)p; }())
    float*  scores = SYM_PTR(float,  g_scores);
    __half* bcH = SYM_PTR(__half, g_bcH); __half* bcL = SYM_PTR(__half, g_bcL);
    __half* zcH = SYM_PTR(__half, g_zcH); __half* zcL = SYM_PTR(__half, g_zcL);
    __half* rwH = SYM_PTR(__half, g_rwH); __half* rwL = SYM_PTR(__half, g_rwL);
    __half* hH  = SYM_PTR(__half, g_hH);
    __half* WrH = SYM_PTR(__half, g_WreadH); __half* WrL = SYM_PTR(__half, g_WreadL);
    __half* WsH = SYM_PTR(__half, g_WsymH);  __half* WsL = SYM_PTR(__half, g_WsymL);
    __half* W1H = SYM_PTR(__half, g_Wc1H);   __half* W1L = SYM_PTR(__half, g_Wc1L);
    __half* W2H = SYM_PTR(__half, g_Wc2H);   __half* W2L = SYM_PTR(__half, g_Wc2L);
    __half* cbH = SYM_PTR(__half, g_cbH);    __half* cbL = SYM_PTR(__half, g_cbL);

    static int once = 0;
    if (!once) {
        cudaFuncSetAttribute(k_tc<3>, cudaFuncAttributeMaxDynamicSharedMemorySize, TC_SMEM);
        cudaFuncSetAttribute(k_tc<2>, cudaFuncAttributeMaxDynamicSharedMemorySize, TC_SMEM);
        once = 1;
    }

    // Launch order: harness prepends ~2 launches; ncu "-s 5 -c 1" captures
    // OUR 4th kernel -> place GEMM1 (k_tc<3>, dominant) at position 4.
    k_cbprep<<<NCODE / 8, 256>>>(cb);                                   // 1 (norms+cvt+init)
    k_route<<<NTOK / 8, 256>>>(syms, Wq, token, outs);                  // 2
    { dim3 g(DLAT / 32, 2 * DLAT / 32);
      k_cvt_wt<<<g, dim3(32, 8)>>>(Wread, WrH, WrL, 2 * DLAT, DLAT); }  // 3
    // 4) zc[:,0:1024] = bc @ Wread^T + bread   (K=2048, N=1024)  [3-term]
    k_tc<3><<<dim3(DLAT / 128, NTOK / 128), TCTHR, TC_SMEM>>>(
        bcH, bcL, 2 * DLAT, WrH, WrL, bread, nullptr, 0,
        nullptr, zcH, zcL, DLAT + DSYM, DLAT, 2 * DLAT);

    { dim3 g(DSYM / 32, DLAT / 32);
      k_cvt_wt<<<g, dim3(32, 8)>>>(Wsym, WsH, WsL, DLAT, DSYM); }
    { dim3 g(DLAT / 32, (DLAT + DSYM) / 32);
      k_cvt_wt<<<g, dim3(32, 8)>>>(Wc1, W1H, W1L, DLAT + DSYM, DLAT); }
    { dim3 g(DLAT / 32, DLAT / 32);
      k_cvt_wt<<<g, dim3(32, 8)>>>(Wc2, W2H, W2L, DLAT, DLAT); }

    // raw = zc[:,0:1024] @ Wsym^T + bsym    (K=1024, N=256)   [3-term]
    k_tc<3><<<dim3(DSYM / 128, NTOK / 128), TCTHR, TC_SMEM>>>(
        zcH, zcL, DLAT + DSYM, WsH, WsL, bsym, nullptr, 0,
        nullptr, rwH, rwL, DSYM, DSYM, DLAT);
    // scores = raw @ cb^T                   (K=256, N=512)    [3-term]
    k_tc<3><<<dim3(NCODE / 128, NTOK / 128), TCTHR, TC_SMEM>>>(
        rwH, rwL, DSYM, cbH, cbL, nullptr, nullptr, 0,
        scores, nullptr, nullptr, 0, NCODE, DSYM);
    k_vq<<<(NTOK * 32 + 255) / 256, 256>>>(cb, out_quant, out_idx);
    // h = relu(zc @ Wc1^T + bc1)            (K=1280, N=1024)  [2-term]
    k_tc<2><<<dim3(DLAT / 128, NTOK / 128), TCTHR, TC_SMEM>>>(
        zcH, nullptr, DLAT + DSYM, W1H, W1L, bc1, nullptr, 1,
        nullptr, hH, nullptr, DLAT, DLAT, DLAT + DSYM);
    // out = h @ Wc2^T + bc2 + token         (K=1024, N=1024)  [2-term]
    k_tc<2><<<dim3(DLAT / 128, NTOK / 128), TCTHR, TC_SMEM>>>(
        hH, nullptr, DLAT, W2H, W2L, bc2, token, 0,
        out_node, nullptr, nullptr, 0, DLAT, DLAT);
    k_mask<<<1, 32>>>(out_mask);
}

// round 16
// speedup vs baseline: 1.5381x; 1.5381x over previous
#include <cuda_runtime.h>
#include <cuda_fp16.h>
#include <cstdint>

#define TDIM   8
#define NTOK   8192
#define DLAT   1024
#define DSYM   256
#define NCODE  512

// ---------------- scratch --------------------------------------------------
static __device__ int    g_used[TDIM];
static __device__ float  g_scores[NTOK * NCODE];
static __device__ float  g_cbn[NCODE];
// half hi/lo buffers
static __device__ __half g_bcH[NTOK * 2 * DLAT],  g_bcL[NTOK * 2 * DLAT];
static __device__ __half g_zcH[NTOK * (DLAT + DSYM)], g_zcL[NTOK * (DLAT + DSYM)];
static __device__ __half g_rwH[NTOK * DSYM],      g_rwL[NTOK * DSYM];
static __device__ __half g_hH[NTOK * DLAT];
static __device__ __half g_WreadH[DLAT * 2 * DLAT], g_WreadL[DLAT * 2 * DLAT];
static __device__ __half g_WsymH[DSYM * DLAT],    g_WsymL[DSYM * DLAT];
static __device__ __half g_Wc1H[DLAT * (DLAT + DSYM)], g_Wc1L[DLAT * (DLAT + DSYM)];
static __device__ __half g_Wc2H[DLAT * DLAT],     g_Wc2L[DLAT * DLAT];
static __device__ __half g_cbH[NCODE * DSYM],     g_cbL[NCODE * DSYM];

static __device__ __forceinline__ void split_h(float v, __half& h, __half& l) {
    h = __float2half_rn(v);
    l = __float2half_rn(v - __half2float(h));
}

// ---------------- small kernels --------------------------------------------
// codebook norms + codebook hi/lo convert + g_used init (one warp per code)
__global__ void k_cbprep(const float* __restrict__ cb) {
    int warp = (blockIdx.x * blockDim.x + threadIdx.x) >> 5;
    int lane = threadIdx.x & 31;
    if (warp >= NCODE) return;
    if (warp == 0 && lane < TDIM) g_used[lane] = 0;
    const float* row = cb + (size_t)warp * DSYM;
    float s = 0.f;
#pragma unroll
    for (int i = 0; i < 8; i++) {
        float v = row[lane + 32 * i];
        s += v * v;
        __half h, l; split_h(v, h, l);
        g_cbH[warp * DSYM + lane + 32 * i] = h;
        g_cbL[warp * DSYM + lane + 32 * i] = l;
    }
#pragma unroll
    for (int o = 16; o; o >>= 1) s += __shfl_xor_sync(0xffffffffu, s, o);
    if (lane == 0) g_cbn[warp] = s;
}

// fused: per-token top-bus argmax + [token | gathered bus] hi/lo build
__global__ void k_route(const float* __restrict__ syms,
                        const float* __restrict__ Wq,
                        const float* __restrict__ token,
                        const float* __restrict__ outs) {
    int warp = (blockIdx.x * blockDim.x + threadIdx.x) >> 5;
    int lane = threadIdx.x & 31;
    if (warp >= NTOK) return;
    float wq[8];
#pragma unroll
    for (int i = 0; i < 8; i++) wq[i] = Wq[lane + 32 * i];
    float best = -3.0e38f;
    int bt = 0;
    for (int t = 0; t < TDIM; t++) {
        const float* row = syms + ((size_t)t * NTOK + warp) * DSYM;
        float s = 0.f;
#pragma unroll
        for (int i = 0; i < 8; i++) s += row[lane + 32 * i] * wq[i];
#pragma unroll
        for (int o = 16; o; o >>= 1) s += __shfl_xor_sync(0xffffffffu, s, o);
        if (s > best) { best = s; bt = t; }   // s identical across lanes -> bt uniform
    }
    if (lane == 0) g_used[bt] = 1;

    const float* srcs[2] = { token + (size_t)warp * DLAT,
                             outs + ((size_t)bt * NTOK + warp) * DLAT };
    size_t obase = (size_t)warp * 2048;
#pragma unroll
    for (int half = 0; half < 2; half++) {
        const float4* src = (const float4*)srcs[half];
        size_t o = obase + half * 1024;
#pragma unroll
        for (int it = 0; it < 4; it++) {
            int e = (it * 32 + lane) * 2;          // float4-pair index
            float4 v0 = src[e];
            float4 v1 = src[e + 1];
            __half h[8], l[8];
            split_h(v0.x, h[0], l[0]); split_h(v0.y, h[1], l[1]);
            split_h(v0.z, h[2], l[2]); split_h(v0.w, h[3], l[3]);
            split_h(v1.x, h[4], l[4]); split_h(v1.y, h[5], l[5]);
            split_h(v1.z, h[6], l[6]); split_h(v1.w, h[7], l[7]);
            __half2 hp[4] = { __halves2half2(h[0], h[1]), __halves2half2(h[2], h[3]),
                              __halves2half2(h[4], h[5]), __halves2half2(h[6], h[7]) };
            __half2 lp[4] = { __halves2half2(l[0], l[1]), __halves2half2(l[2], l[3]),
                              __halves2half2(l[4], l[5]), __halves2half2(l[6], l[7]) };
            *(uint4*)(g_bcH + o + e * 4) = *(uint4*)hp;
            *(uint4*)(g_bcL + o + e * 4) = *(uint4*)lp;
        }
    }
}

// transpose+convert: W[K,N] fp32 -> H/L [N,K] half
__global__ void k_cvt_wt(const float* __restrict__ W, __half* __restrict__ H,
                         __half* __restrict__ L, int K, int N) {
    __shared__ float t[32][33];
    int n0 = blockIdx.x * 32, k0 = blockIdx.y * 32;
    int tx = threadIdx.x, ty = threadIdx.y;    // (32, 8)
#pragma unroll
    for (int i = 0; i < 4; i++)
        t[ty + 8 * i][tx] = W[(size_t)(k0 + ty + 8 * i) * N + n0 + tx];
    __syncthreads();
#pragma unroll
    for (int i = 0; i < 4; i++) {
        float v = t[tx][ty + 8 * i];
        __half h, l; split_h(v, h, l);
        size_t o = (size_t)(n0 + ty + 8 * i) * K + k0 + tx;
        H[o] = h; L[o] = l;
    }
}

// VQ argmin + gathers: fp32 quant out + hi halves into zc cols 1024..1279
__global__ void k_vq(const float* __restrict__ cb,
                     float* __restrict__ quant_out,
                     float* __restrict__ idx_out) {
    int warp = (blockIdx.x * blockDim.x + threadIdx.x) >> 5;
    int lane = threadIdx.x & 31;
    if (warp >= NTOK) return;
    const float* srow = g_scores + (size_t)warp * NCODE;
    float best = 3.0e38f;
    int bi = 0x7fffffff;
    for (int c = lane; c < NCODE; c += 32) {
        float d = g_cbn[c] - 2.f * srow[c];
        if (d < best) { best = d; bi = c; }
    }
#pragma unroll
    for (int o = 16; o; o >>= 1) {
        float ov = __shfl_xor_sync(0xffffffffu, best, o);
        int   oi = __shfl_xor_sync(0xffffffffu, bi, o);
        if (ov < best || (ov == best && oi < bi)) { best = ov; bi = oi; }
    }
    const float4* q = (const float4*)(cb + (size_t)bi * DSYM);
    float4* dst = (float4*)(quant_out + (size_t)warp * DSYM);
#pragma unroll
    for (int i = lane; i < DSYM / 4; i += 32) dst[i] = q[i];
    const float4* qh = (const float4*)(g_cbH + (size_t)bi * DSYM);
    float4* dH = (float4*)(g_zcH + (size_t)warp * 1280 + 1024);
#pragma unroll
    for (int i = lane; i < DSYM / 8; i += 32) dH[i] = qh[i];
    if (lane == 0) idx_out[warp] = (float)bi;
}

__global__ void k_mask(float* __restrict__ mask_out) {
    int t = threadIdx.x;
    if (t < TDIM) mask_out[t] = (g_used[t] == 0) ? 1.f : 0.f;
}

// ---------------- fp16 split tensor GEMM: cp.async + ldmatrix ---------------
// C[M,N] = A[M,K] @ B^T (B stored [N,K]).
// NT=3: D = AhBh + AhBl + AlBh;  NT=2: D = AhBh + AhBl (skip Al)
// Epilogue fully templated (BIAS/RELU/RES/OM) to strip dead code + registers.
// OM: 0 = fp32 C;  1 = half hi+lo;  2 = half hi only.
// CTA 128x128, BK=32, 4 warps (2x2) @ 64x64, 2-stage cp.async,
// ONE sync per k-tile, 64KB smem -> 2 CTAs/SM.
#define STG_B 32768
#define TC_SMEM (2 * STG_B)           // 65536
#define TCTHR 128

#define MMA16816(d, a, b)                                             \
    asm volatile(                                                     \
        "mma.sync.aligned.m16n8k16.row.col.f32.f16.f16.f32 "          \
        "{%0,%1,%2,%3},{%4,%5,%6,%7},{%8,%9},{%0,%1,%2,%3};"          \
        : "+f"(d[0]), "+f"(d[1]), "+f"(d[2]), "+f"(d[3])              \
        : "r"(a[0]), "r"(a[1]), "r"(a[2]), "r"(a[3]),                 \
          "r"(b[0]), "r"(b[1]))

static __device__ __forceinline__ uint32_t smem_u32(const void* p) {
    uint32_t a;
    asm("{ .reg .u64 t; cvta.to.shared.u64 t, %1; cvt.u32.u64 %0, t; }"
        : "=r"(a) : "l"(p));
    return a;
}
static __device__ __forceinline__ void cp16(uint32_t dst, const void* src) {
    asm volatile("cp.async.cg.shared.global [%0], [%1], 16;"
                 :: "r"(dst), "l"(src) : "memory");
}
static __device__ __forceinline__ void ldm4(uint32_t& r0, uint32_t& r1,
                                            uint32_t& r2, uint32_t& r3, uint32_t a) {
    asm volatile("ldmatrix.sync.aligned.m8n8.x4.shared.b16 {%0,%1,%2,%3}, [%4];"
                 : "=r"(r0), "=r"(r1), "=r"(r2), "=r"(r3) : "r"(a));
}

template <int NT, int BIAS, int RELU, int RES, int OM>
__global__ __launch_bounds__(TCTHR, 2)
void k_tc(const __half* __restrict__ Ah, const __half* __restrict__ Al, int lda,
          const __half* __restrict__ Bh, const __half* __restrict__ Bl,
          const float* __restrict__ bias, const float* __restrict__ res,
          float* __restrict__ C, __half* __restrict__ Ch, __half* __restrict__ Cl,
          int ldch, int N, int K)
{
    extern __shared__ char sm[];
    const uint32_t sb = smem_u32(sm);
    const int tid = threadIdx.x;
    const int wid = tid >> 5, lane = tid & 31;
    const int wm = wid & 1, wn = wid >> 1;       // warp grid 2(m) x 2(n)
    const int g = lane >> 2, t4 = lane & 3;
    const int bm = blockIdx.y * 128, bn = blockIdx.x * 128;

    int cr[4], cc[4];
#pragma unroll
    for (int l = 0; l < 4; l++) {
        int c = tid + l * TCTHR;
        cr[l] = c >> 2;
        cc[l] = c & 3;
    }

    auto issue_stage = [&](int t) {
        const int kt = t * 32;
        const uint32_t s0 = sb + (t & 1) * STG_B;
#pragma unroll
        for (int l = 0; l < 4; l++) {
            int r = cr[l], ch = cc[l];
            uint32_t d = s0 + r * 64 + ((ch ^ ((r >> 1) & 3)) << 4);
            size_t ga = (size_t)(bm + r) * lda + kt + ch * 8;
            cp16(d, Ah + ga);
            if (NT == 3) cp16(d + 8192, Al + ga);
            size_t gb = (size_t)(bn + r) * K + kt + ch * 8;
            cp16(d + 16384,  Bh + gb);
            cp16(d + 24576,  Bl + gb);
        }
        asm volatile("cp.async.commit_group;" ::: "memory");
    };

    const int amb = (lane & 7) + 8 * ((lane >> 3) & 1);
    const int akl = (lane >> 4) & 1;
    const int swa = (amb >> 1) & 3;
    const int bnb = (lane & 7) + 8 * ((lane >> 4) & 1);
    const int bkl = (lane >> 3) & 1;
    const int swb = (bnb >> 1) & 3;

    float acc[4][8][4] = {};
    const int T = K / 32;

    issue_stage(0);

    for (int t = 0; t < T; t++) {
        asm volatile("cp.async.wait_group 0;" ::: "memory");
        __syncthreads();
        // Buffer (t+1)&1 == (t-1)&1 already consumed: no extra barrier.
        if (t + 1 < T) issue_stage(t + 1);

        const uint32_t s0 = sb + (t & 1) * STG_B;
        const uint32_t aH = s0, aL = s0 + 8192;
        const uint32_t bH = s0 + 16384, bL = s0 + 24576;
#pragma unroll
        for (int s = 0; s < 2; s++) {
            uint32_t bh[8][2], bl[8][2];
#pragma unroll
            for (int jp = 0; jp < 4; jp++) {
                uint32_t off = (uint32_t)(wn * 64 + jp * 16 + bnb) * 64
                             + (((s * 2 + bkl) ^ swb) << 4);
                ldm4(bh[2 * jp][0], bh[2 * jp][1], bh[2 * jp + 1][0], bh[2 * jp + 1][1],
                     bH + off);
                ldm4(bl[2 * jp][0], bl[2 * jp][1], bl[2 * jp + 1][0], bl[2 * jp + 1][1],
                     bL + off);
            }
#pragma unroll
            for (int i = 0; i < 4; i++) {
                uint32_t off = (uint32_t)(wm * 64 + i * 16 + amb) * 64
                             + (((s * 2 + akl) ^ swa) << 4);
                uint32_t ah[4], al[4];
                ldm4(ah[0], ah[1], ah[2], ah[3], aH + off);
                if (NT == 3) ldm4(al[0], al[1], al[2], al[3], aL + off);
#pragma unroll
                for (int j = 0; j < 8; j++) {
                    MMA16816(acc[i][j], ah, bh[j]);
                    MMA16816(acc[i][j], ah, bl[j]);
                    if (NT == 3) MMA16816(acc[i][j], al, bh[j]);
                }
            }
        }
    }

    // ---- epilogue (templated: only the needed path is compiled) ----
#pragma unroll
    for (int i = 0; i < 4; i++) {
        int row0 = bm + wm * 64 + i * 16 + g;
#pragma unroll
        for (int j = 0; j < 8; j++) {
            int col = bn + wn * 64 + j * 8 + 2 * t4;
            float2 v0 = make_float2(acc[i][j][0], acc[i][j][1]);
            float2 v1 = make_float2(acc[i][j][2], acc[i][j][3]);
            if (BIAS) {
                float2 bv = *(const float2*)(bias + col);
                v0.x += bv.x; v0.y += bv.y;
                v1.x += bv.x; v1.y += bv.y;
            }
            if (RELU) {
                v0.x = fmaxf(v0.x, 0.f); v0.y = fmaxf(v0.y, 0.f);
                v1.x = fmaxf(v1.x, 0.f); v1.y = fmaxf(v1.y, 0.f);
            }
            if (OM == 0) {
                size_t o0 = (size_t)row0 * N + col;
                size_t o1 = (size_t)(row0 + 8) * N + col;
                if (RES) {
                    float2 r0 = *(const float2*)(res + o0);
                    float2 r1 = *(const float2*)(res + o1);
                    v0.x += r0.x; v0.y += r0.y;
                    v1.x += r1.x; v1.y += r1.y;
                }
                *(float2*)(C + o0) = v0;
                *(float2*)(C + o1) = v1;
            } else {
                size_t p0 = (size_t)row0 * ldch + col;
                size_t p1 = (size_t)(row0 + 8) * ldch + col;
                __half h0 = __float2half_rn(v0.x), h1 = __float2half_rn(v0.y);
                __half h2 = __float2half_rn(v1.x), h3 = __float2half_rn(v1.y);
                *(__half2*)(Ch + p0) = __halves2half2(h0, h1);
                *(__half2*)(Ch + p1) = __halves2half2(h2, h3);
                if (OM == 1) {
                    __half l0 = __float2half_rn(v0.x - __half2float(h0));
                    __half l1 = __float2half_rn(v0.y - __half2float(h1));
                    __half l2 = __float2half_rn(v1.x - __half2float(h2));
                    __half l3 = __float2half_rn(v1.y - __half2float(h3));
                    *(__half2*)(Cl + p0) = __halves2half2(l0, l1);
                    *(__half2*)(Cl + p1) = __halves2half2(l2, l3);
                }
            }
        }
    }
}

// ---------------- launch ----------------------------------------------------
extern "C" void kernel_launch(void* const* d_in, const int* in_sizes, int n_in,
                              void* d_out, int out_size)
{
    const float* token = (const float*)d_in[0];
    const float* syms  = (const float*)d_in[1];
    const float* outs  = (const float*)d_in[3];
    const float* Wq    = (const float*)d_in[5];
    const float* Wread = (const float*)d_in[7];
    const float* bread = (const float*)d_in[8];
    const float* Wsym  = (const float*)d_in[9];
    const float* bsym  = (const float*)d_in[10];
    const float* Wc1   = (const float*)d_in[11];
    const float* bc1   = (const float*)d_in[12];
    const float* Wc2   = (const float*)d_in[13];
    const float* bc2   = (const float*)d_in[14];
    const float* cb    = (const float*)d_in[15];

    float* out        = (float*)d_out;
    float* out_node   = out;
    float* out_quant  = out + (size_t)NTOK * DLAT;
    float* out_idx    = out_quant + (size_t)NTOK * DSYM;
    float* out_mask   = out_idx + NTOK;

#define SYM_PTR(T, sym) ([]{ void* p; cudaGetSymbolAddress(&p, sym); return (T*)p; }())
    float*  scores = SYM_PTR(float,  g_scores);
    __half* bcH = SYM_PTR(__half, g_bcH); __half* bcL = SYM_PTR(__half, g_bcL);
    __half* zcH = SYM_PTR(__half, g_zcH); __half* zcL = SYM_PTR(__half, g_zcL);
    __half* rwH = SYM_PTR(__half, g_rwH); __half* rwL = SYM_PTR(__half, g_rwL);
    __half* hH  = SYM_PTR(__half, g_hH);
    __half* WrH = SYM_PTR(__half, g_WreadH); __half* WrL = SYM_PTR(__half, g_WreadL);
    __half* WsH = SYM_PTR(__half, g_WsymH);  __half* WsL = SYM_PTR(__half, g_WsymL);
    __half* W1H = SYM_PTR(__half, g_Wc1H);   __half* W1L = SYM_PTR(__half, g_Wc1L);
    __half* W2H = SYM_PTR(__half, g_Wc2H);   __half* W2L = SYM_PTR(__half, g_Wc2L);
    __half* cbH = SYM_PTR(__half, g_cbH);    __half* cbL = SYM_PTR(__half, g_cbL);

    static int once = 0;
    if (!once) {
        cudaFuncSetAttribute(k_tc<3,1,0,0,1>, cudaFuncAttributeMaxDynamicSharedMemorySize, TC_SMEM);
        cudaFuncSetAttribute(k_tc<3,0,0,0,0>, cudaFuncAttributeMaxDynamicSharedMemorySize, TC_SMEM);
        cudaFuncSetAttribute(k_tc<2,1,1,0,2>, cudaFuncAttributeMaxDynamicSharedMemorySize, TC_SMEM);
        cudaFuncSetAttribute(k_tc<2,1,0,1,0>, cudaFuncAttributeMaxDynamicSharedMemorySize, TC_SMEM);
        once = 1;
    }

    // R14-proven launch order (GEMM1 after weight converts).
    k_cbprep<<<NCODE / 8, 256>>>(cb);
    k_route<<<NTOK / 8, 256>>>(syms, Wq, token, outs);
    { dim3 g(DLAT / 32, 2 * DLAT / 32);
      k_cvt_wt<<<g, dim3(32, 8)>>>(Wread, WrH, WrL, 2 * DLAT, DLAT); }
    { dim3 g(DSYM / 32, DLAT / 32);
      k_cvt_wt<<<g, dim3(32, 8)>>>(Wsym, WsH, WsL, DLAT, DSYM); }
    { dim3 g(DLAT / 32, (DLAT + DSYM) / 32);
      k_cvt_wt<<<g, dim3(32, 8)>>>(Wc1, W1H, W1L, DLAT + DSYM, DLAT); }

    // 1) zc[:,0:1024] = bc @ Wread^T + bread   (K=2048, N=1024)  [3-term, hi/lo out]
    k_tc<3,1,0,0,1><<<dim3(DLAT / 128, NTOK / 128), TCTHR, TC_SMEM>>>(
        bcH, bcL, 2 * DLAT, WrH, WrL, bread, nullptr,
        nullptr, zcH, zcL, DLAT + DSYM, DLAT, 2 * DLAT);

    { dim3 g(DLAT / 32, DLAT / 32);
      k_cvt_wt<<<g, dim3(32, 8)>>>(Wc2, W2H, W2L, DLAT, DLAT); }

    // 2) raw = zc[:,0:1024] @ Wsym^T + bsym    (K=1024, N=256)   [3-term, hi/lo out]
    k_tc<3,1,0,0,1><<<dim3(DSYM / 128, NTOK / 128), TCTHR, TC_SMEM>>>(
        zcH, zcL, DLAT + DSYM, WsH, WsL, bsym, nullptr,
        nullptr, rwH, rwL, DSYM, DSYM, DLAT);
    // 3) scores = raw @ cb^T                   (K=256, N=512)    [3-term, f32 out]
    k_tc<3,0,0,0,0><<<dim3(NCODE / 128, NTOK / 128), TCTHR, TC_SMEM>>>(
        rwH, rwL, DSYM, cbH, cbL, nullptr, nullptr,
        scores, nullptr, nullptr, 0, NCODE, DSYM);
    k_vq<<<(NTOK * 32 + 255) / 256, 256>>>(cb, out_quant, out_idx);
    // 4) h = relu(zc @ Wc1^T + bc1)            (K=1280, N=1024)  [2-term, hi out]
    k_tc<2,1,1,0,2><<<dim3(DLAT / 128, NTOK / 128), TCTHR, TC_SMEM>>>(
        zcH, nullptr, DLAT + DSYM, W1H, W1L, bc1, nullptr,
        nullptr, hH, nullptr, DLAT, DLAT, DLAT + DSYM);
    // 5) out = h @ Wc2^T + bc2 + token         (K=1024, N=1024)  [2-term, f32+res]
    k_tc<2,1,0,1,0><<<dim3(DLAT / 128, NTOK / 128), TCTHR, TC_SMEM>>>(
        hH, nullptr, DLAT, W2H, W2L, bc2, token,
        out_node, nullptr, nullptr, 0, DLAT, DLAT);
    k_mask<<<1, 32>>>(out_mask);
}

// round 17
// speedup vs baseline: 1.5446x; 1.0042x over previous
#include <cuda_runtime.h>
#include <cuda_fp16.h>
#include <cstdint>

#define TDIM   8
#define NTOK   8192
#define DLAT   1024
#define DSYM   256
#define NCODE  512

// ---------------- scratch --------------------------------------------------
static __device__ int    g_used[TDIM];
static __device__ float  g_scores[NTOK * NCODE];
static __device__ float  g_cbn[NCODE];
// half hi/lo buffers
static __device__ __half g_bcH[NTOK * 2 * DLAT],  g_bcL[NTOK * 2 * DLAT];
static __device__ __half g_zcH[NTOK * (DLAT + DSYM)], g_zcL[NTOK * (DLAT + DSYM)];
static __device__ __half g_rwH[NTOK * DSYM],      g_rwL[NTOK * DSYM];
static __device__ __half g_hH[NTOK * DLAT];
static __device__ __half g_WreadH[DLAT * 2 * DLAT], g_WreadL[DLAT * 2 * DLAT];
static __device__ __half g_WsymH[DSYM * DLAT],    g_WsymL[DSYM * DLAT];
static __device__ __half g_Wc1H[DLAT * (DLAT + DSYM)], g_Wc1L[DLAT * (DLAT + DSYM)];
static __device__ __half g_Wc2H[DLAT * DLAT],     g_Wc2L[DLAT * DLAT];
static __device__ __half g_cbH[NCODE * DSYM],     g_cbL[NCODE * DSYM];

static __device__ __forceinline__ void split_h(float v, __half& h, __half& l) {
    h = __float2half_rn(v);
    l = __float2half_rn(v - __half2float(h));
}

// ---------------- small kernels --------------------------------------------
// codebook norms + codebook hi/lo convert + g_used init (one warp per code)
__global__ void k_cbprep(const float* __restrict__ cb) {
    int warp = (blockIdx.x * blockDim.x + threadIdx.x) >> 5;
    int lane = threadIdx.x & 31;
    if (warp >= NCODE) return;
    if (warp == 0 && lane < TDIM) g_used[lane] = 0;
    const float* row = cb + (size_t)warp * DSYM;
    float s = 0.f;
#pragma unroll
    for (int i = 0; i < 8; i++) {
        float v = row[lane + 32 * i];
        s += v * v;
        __half h, l; split_h(v, h, l);
        g_cbH[warp * DSYM + lane + 32 * i] = h;
        g_cbL[warp * DSYM + lane + 32 * i] = l;
    }
#pragma unroll
    for (int o = 16; o; o >>= 1) s += __shfl_xor_sync(0xffffffffu, s, o);
    if (lane == 0) g_cbn[warp] = s;
}

// fused: per-token top-bus argmax + [token | gathered bus] hi/lo build
__global__ void k_route(const float* __restrict__ syms,
                        const float* __restrict__ Wq,
                        const float* __restrict__ token,
                        const float* __restrict__ outs) {
    int warp = (blockIdx.x * blockDim.x + threadIdx.x) >> 5;
    int lane = threadIdx.x & 31;
    if (warp >= NTOK) return;
    float wq[8];
#pragma unroll
    for (int i = 0; i < 8; i++) wq[i] = Wq[lane + 32 * i];
    float best = -3.0e38f;
    int bt = 0;
    for (int t = 0; t < TDIM; t++) {
        const float* row = syms + ((size_t)t * NTOK + warp) * DSYM;
        float s = 0.f;
#pragma unroll
        for (int i = 0; i < 8; i++) s += row[lane + 32 * i] * wq[i];
#pragma unroll
        for (int o = 16; o; o >>= 1) s += __shfl_xor_sync(0xffffffffu, s, o);
        if (s > best) { best = s; bt = t; }   // s identical across lanes -> bt uniform
    }
    if (lane == 0) g_used[bt] = 1;

    const float* srcs[2] = { token + (size_t)warp * DLAT,
                             outs + ((size_t)bt * NTOK + warp) * DLAT };
    size_t obase = (size_t)warp * 2048;
#pragma unroll
    for (int half = 0; half < 2; half++) {
        const float4* src = (const float4*)srcs[half];
        size_t o = obase + half * 1024;
#pragma unroll
        for (int it = 0; it < 4; it++) {
            int e = (it * 32 + lane) * 2;          // float4-pair index
            float4 v0 = src[e];
            float4 v1 = src[e + 1];
            __half h[8], l[8];
            split_h(v0.x, h[0], l[0]); split_h(v0.y, h[1], l[1]);
            split_h(v0.z, h[2], l[2]); split_h(v0.w, h[3], l[3]);
            split_h(v1.x, h[4], l[4]); split_h(v1.y, h[5], l[5]);
            split_h(v1.z, h[6], l[6]); split_h(v1.w, h[7], l[7]);
            __half2 hp[4] = { __halves2half2(h[0], h[1]), __halves2half2(h[2], h[3]),
                              __halves2half2(h[4], h[5]), __halves2half2(h[6], h[7]) };
            __half2 lp[4] = { __halves2half2(l[0], l[1]), __halves2half2(l[2], l[3]),
                              __halves2half2(l[4], l[5]), __halves2half2(l[6], l[7]) };
            *(uint4*)(g_bcH + o + e * 4) = *(uint4*)hp;
            *(uint4*)(g_bcL + o + e * 4) = *(uint4*)lp;
        }
    }
}

// transpose+convert: W[K,N] fp32 -> H/L [N,K] half
__global__ void k_cvt_wt(const float* __restrict__ W, __half* __restrict__ H,
                         __half* __restrict__ L, int K, int N) {
    __shared__ float t[32][33];
    int n0 = blockIdx.x * 32, k0 = blockIdx.y * 32;
    int tx = threadIdx.x, ty = threadIdx.y;    // (32, 8)
#pragma unroll
    for (int i = 0; i < 4; i++)
        t[ty + 8 * i][tx] = W[(size_t)(k0 + ty + 8 * i) * N + n0 + tx];
    __syncthreads();
#pragma unroll
    for (int i = 0; i < 4; i++) {
        float v = t[tx][ty + 8 * i];
        __half h, l; split_h(v, h, l);
        size_t o = (size_t)(n0 + ty + 8 * i) * K + k0 + tx;
        H[o] = h; L[o] = l;
    }
}

// VQ argmin + gathers: fp32 quant out + hi halves into zc cols 1024..1279
__global__ void k_vq(const float* __restrict__ cb,
                     float* __restrict__ quant_out,
                     float* __restrict__ idx_out) {
    int warp = (blockIdx.x * blockDim.x + threadIdx.x) >> 5;
    int lane = threadIdx.x & 31;
    if (warp >= NTOK) return;
    const float* srow = g_scores + (size_t)warp * NCODE;
    float best = 3.0e38f;
    int bi = 0x7fffffff;
    for (int c = lane; c < NCODE; c += 32) {
        float d = g_cbn[c] - 2.f * srow[c];
        if (d < best) { best = d; bi = c; }
    }
#pragma unroll
    for (int o = 16; o; o >>= 1) {
        float ov = __shfl_xor_sync(0xffffffffu, best, o);
        int   oi = __shfl_xor_sync(0xffffffffu, bi, o);
        if (ov < best || (ov == best && oi < bi)) { best = ov; bi = oi; }
    }
    const float4* q = (const float4*)(cb + (size_t)bi * DSYM);
    float4* dst = (float4*)(quant_out + (size_t)warp * DSYM);
#pragma unroll
    for (int i = lane; i < DSYM / 4; i += 32) dst[i] = q[i];
    const float4* qh = (const float4*)(g_cbH + (size_t)bi * DSYM);
    float4* dH = (float4*)(g_zcH + (size_t)warp * 1280 + 1024);
#pragma unroll
    for (int i = lane; i < DSYM / 8; i += 32) dH[i] = qh[i];
    if (lane == 0) idx_out[warp] = (float)bi;
}

__global__ void k_mask(float* __restrict__ mask_out) {
    int t = threadIdx.x;
    if (t < TDIM) mask_out[t] = (g_used[t] == 0) ? 1.f : 0.f;
}

// ---------------- fp16 split tensor GEMM: cp.async + ldmatrix ---------------
// C[M,N] = A[M,K] @ B^T (B stored [N,K]).
// NT=3: D = AhBh + AhBl + AlBh;  NT=2: D = AhBh + AhBl (skip Al)
// MMA terms issued as separate j-passes so consecutive MMAs hit DIFFERENT
// accumulators (breaks acc RAW chains; 8-deep independence per pass).
// Epilogue templated (BIAS/RELU/RES/OM). OM: 0=f32, 1=half hi+lo, 2=half hi.
// CTA 128x128, BK=32, 4 warps (2x2) @ 64x64, 2-stage cp.async,
// ONE sync per k-tile, 64KB smem -> 2 CTAs/SM.
#define STG_B 32768
#define TC_SMEM (2 * STG_B)           // 65536
#define TCTHR 128

#define MMA16816(d, a, b)                                             \
    asm volatile(                                                     \
        "mma.sync.aligned.m16n8k16.row.col.f32.f16.f16.f32 "          \
        "{%0,%1,%2,%3},{%4,%5,%6,%7},{%8,%9},{%0,%1,%2,%3};"          \
        : "+f"(d[0]), "+f"(d[1]), "+f"(d[2]), "+f"(d[3])              \
        : "r"(a[0]), "r"(a[1]), "r"(a[2]), "r"(a[3]),                 \
          "r"(b[0]), "r"(b[1]))

static __device__ __forceinline__ uint32_t smem_u32(const void* p) {
    uint32_t a;
    asm("{ .reg .u64 t; cvta.to.shared.u64 t, %1; cvt.u32.u64 %0, t; }"
        : "=r"(a) : "l"(p));
    return a;
}
static __device__ __forceinline__ void cp16(uint32_t dst, const void* src) {
    asm volatile("cp.async.cg.shared.global [%0], [%1], 16;"
                 :: "r"(dst), "l"(src) : "memory");
}
static __device__ __forceinline__ void ldm4(uint32_t& r0, uint32_t& r1,
                                            uint32_t& r2, uint32_t& r3, uint32_t a) {
    asm volatile("ldmatrix.sync.aligned.m8n8.x4.shared.b16 {%0,%1,%2,%3}, [%4];"
                 : "=r"(r0), "=r"(r1), "=r"(r2), "=r"(r3) : "r"(a));
}

template <int NT, int BIAS, int RELU, int RES, int OM>
__global__ __launch_bounds__(TCTHR, 2)
void k_tc(const __half* __restrict__ Ah, const __half* __restrict__ Al, int lda,
          const __half* __restrict__ Bh, const __half* __restrict__ Bl,
          const float* __restrict__ bias, const float* __restrict__ res,
          float* __restrict__ C, __half* __restrict__ Ch, __half* __restrict__ Cl,
          int ldch, int N, int K)
{
    extern __shared__ char sm[];
    const uint32_t sb = smem_u32(sm);
    const int tid = threadIdx.x;
    const int wid = tid >> 5, lane = tid & 31;
    const int wm = wid & 1, wn = wid >> 1;       // warp grid 2(m) x 2(n)
    const int g = lane >> 2, t4 = lane & 3;
    const int bm = blockIdx.y * 128, bn = blockIdx.x * 128;

    int cr[4], cc[4];
#pragma unroll
    for (int l = 0; l < 4; l++) {
        int c = tid + l * TCTHR;
        cr[l] = c >> 2;
        cc[l] = c & 3;
    }

    auto issue_stage = [&](int t) {
        const int kt = t * 32;
        const uint32_t s0 = sb + (t & 1) * STG_B;
#pragma unroll
        for (int l = 0; l < 4; l++) {
            int r = cr[l], ch = cc[l];
            uint32_t d = s0 + r * 64 + ((ch ^ ((r >> 1) & 3)) << 4);
            size_t ga = (size_t)(bm + r) * lda + kt + ch * 8;
            cp16(d, Ah + ga);
            if (NT == 3) cp16(d + 8192, Al + ga);
            size_t gb = (size_t)(bn + r) * K + kt + ch * 8;
            cp16(d + 16384,  Bh + gb);
            cp16(d + 24576,  Bl + gb);
        }
        asm volatile("cp.async.commit_group;" ::: "memory");
    };

    const int amb = (lane & 7) + 8 * ((lane >> 3) & 1);
    const int akl = (lane >> 4) & 1;
    const int swa = (amb >> 1) & 3;
    const int bnb = (lane & 7) + 8 * ((lane >> 4) & 1);
    const int bkl = (lane >> 3) & 1;
    const int swb = (bnb >> 1) & 3;

    float acc[4][8][4] = {};
    const int T = K / 32;

    issue_stage(0);

    for (int t = 0; t < T; t++) {
        asm volatile("cp.async.wait_group 0;" ::: "memory");
        __syncthreads();
        // Buffer (t+1)&1 == (t-1)&1 already consumed: no extra barrier.
        if (t + 1 < T) issue_stage(t + 1);

        const uint32_t s0 = sb + (t & 1) * STG_B;
        const uint32_t aH = s0, aL = s0 + 8192;
        const uint32_t bH = s0 + 16384, bL = s0 + 24576;
#pragma unroll
        for (int s = 0; s < 2; s++) {
            uint32_t bh[8][2], bl[8][2];
#pragma unroll
            for (int jp = 0; jp < 4; jp++) {
                uint32_t off = (uint32_t)(wn * 64 + jp * 16 + bnb) * 64
                             + (((s * 2 + bkl) ^ swb) << 4);
                ldm4(bh[2 * jp][0], bh[2 * jp][1], bh[2 * jp + 1][0], bh[2 * jp + 1][1],
                     bH + off);
                ldm4(bl[2 * jp][0], bl[2 * jp][1], bl[2 * jp + 1][0], bl[2 * jp + 1][1],
                     bL + off);
            }
#pragma unroll
            for (int i = 0; i < 4; i++) {
                uint32_t off = (uint32_t)(wm * 64 + i * 16 + amb) * 64
                             + (((s * 2 + akl) ^ swa) << 4);
                uint32_t ah[4], al[4];
                ldm4(ah[0], ah[1], ah[2], ah[3], aH + off);
                if (NT == 3) ldm4(al[0], al[1], al[2], al[3], aL + off);
                // three independent j-passes: consecutive MMAs write
                // different accumulators (no RAW chain)
#pragma unroll
                for (int j = 0; j < 8; j++) MMA16816(acc[i][j], ah, bh[j]);
#pragma unroll
                for (int j = 0; j < 8; j++) MMA16816(acc[i][j], ah, bl[j]);
                if (NT == 3) {
#pragma unroll
                    for (int j = 0; j < 8; j++) MMA16816(acc[i][j], al, bh[j]);
                }
            }
        }
    }

    // ---- epilogue (templated: only the needed path is compiled) ----
#pragma unroll
    for (int i = 0; i < 4; i++) {
        int row0 = bm + wm * 64 + i * 16 + g;
#pragma unroll
        for (int j = 0; j < 8; j++) {
            int col = bn + wn * 64 + j * 8 + 2 * t4;
            float2 v0 = make_float2(acc[i][j][0], acc[i][j][1]);
            float2 v1 = make_float2(acc[i][j][2], acc[i][j][3]);
            if (BIAS) {
                float2 bv = *(const float2*)(bias + col);
                v0.x += bv.x; v0.y += bv.y;
                v1.x += bv.x; v1.y += bv.y;
            }
            if (RELU) {
                v0.x = fmaxf(v0.x, 0.f); v0.y = fmaxf(v0.y, 0.f);
                v1.x = fmaxf(v1.x, 0.f); v1.y = fmaxf(v1.y, 0.f);
            }
            if (OM == 0) {
                size_t o0 = (size_t)row0 * N + col;
                size_t o1 = (size_t)(row0 + 8) * N + col;
                if (RES) {
                    float2 r0 = *(const float2*)(res + o0);
                    float2 r1 = *(const float2*)(res + o1);
                    v0.x += r0.x; v0.y += r0.y;
                    v1.x += r1.x; v1.y += r1.y;
                }
                *(float2*)(C + o0) = v0;
                *(float2*)(C + o1) = v1;
            } else {
                size_t p0 = (size_t)row0 * ldch + col;
                size_t p1 = (size_t)(row0 + 8) * ldch + col;
                __half h0 = __float2half_rn(v0.x), h1 = __float2half_rn(v0.y);
                __half h2 = __float2half_rn(v1.x), h3 = __float2half_rn(v1.y);
                *(__half2*)(Ch + p0) = __halves2half2(h0, h1);
                *(__half2*)(Ch + p1) = __halves2half2(h2, h3);
                if (OM == 1) {
                    __half l0 = __float2half_rn(v0.x - __half2float(h0));
                    __half l1 = __float2half_rn(v0.y - __half2float(h1));
                    __half l2 = __float2half_rn(v1.x - __half2float(h2));
                    __half l3 = __float2half_rn(v1.y - __half2float(h3));
                    *(__half2*)(Cl + p0) = __halves2half2(l0, l1);
                    *(__half2*)(Cl + p1) = __halves2half2(l2, l3);
                }
            }
        }
    }
}

// ---------------- launch ----------------------------------------------------
extern "C" void kernel_launch(void* const* d_in, const int* in_sizes, int n_in,
                              void* d_out, int out_size)
{
    const float* token = (const float*)d_in[0];
    const float* syms  = (const float*)d_in[1];
    const float* outs  = (const float*)d_in[3];
    const float* Wq    = (const float*)d_in[5];
    const float* Wread = (const float*)d_in[7];
    const float* bread = (const float*)d_in[8];
    const float* Wsym  = (const float*)d_in[9];
    const float* bsym  = (const float*)d_in[10];
    const float* Wc1   = (const float*)d_in[11];
    const float* bc1   = (const float*)d_in[12];
    const float* Wc2   = (const float*)d_in[13];
    const float* bc2   = (const float*)d_in[14];
    const float* cb    = (const float*)d_in[15];

    float* out        = (float*)d_out;
    float* out_node   = out;
    float* out_quant  = out + (size_t)NTOK * DLAT;
    float* out_idx    = out_quant + (size_t)NTOK * DSYM;
    float* out_mask   = out_idx + NTOK;

#define SYM_PTR(T, sym) ([]{ void* p; cudaGetSymbolAddress(&p, sym); return (T*)p; }())
    float*  scores = SYM_PTR(float,  g_scores);
    __half* bcH = SYM_PTR(__half, g_bcH); __half* bcL = SYM_PTR(__half, g_bcL);
    __half* zcH = SYM_PTR(__half, g_zcH); __half* zcL = SYM_PTR(__half, g_zcL);
    __half* rwH = SYM_PTR(__half, g_rwH); __half* rwL = SYM_PTR(__half, g_rwL);
    __half* hH  = SYM_PTR(__half, g_hH);
    __half* WrH = SYM_PTR(__half, g_WreadH); __half* WrL = SYM_PTR(__half, g_WreadL);
    __half* WsH = SYM_PTR(__half, g_WsymH);  __half* WsL = SYM_PTR(__half, g_WsymL);
    __half* W1H = SYM_PTR(__half, g_Wc1H);   __half* W1L = SYM_PTR(__half, g_Wc1L);
    __half* W2H = SYM_PTR(__half, g_Wc2H);   __half* W2L = SYM_PTR(__half, g_Wc2L);
    __half* cbH = SYM_PTR(__half, g_cbH);    __half* cbL = SYM_PTR(__half, g_cbL);

    static int once = 0;
    if (!once) {
        cudaFuncSetAttribute(k_tc<3,1,0,0,1>, cudaFuncAttributeMaxDynamicSharedMemorySize, TC_SMEM);
        cudaFuncSetAttribute(k_tc<3,0,0,0,0>, cudaFuncAttributeMaxDynamicSharedMemorySize, TC_SMEM);
        cudaFuncSetAttribute(k_tc<2,1,1,0,2>, cudaFuncAttributeMaxDynamicSharedMemorySize, TC_SMEM);
        cudaFuncSetAttribute(k_tc<2,1,0,1,0>, cudaFuncAttributeMaxDynamicSharedMemorySize, TC_SMEM);
        once = 1;
    }

    k_cbprep<<<NCODE / 8, 256>>>(cb);
    k_route<<<NTOK / 8, 256>>>(syms, Wq, token, outs);
    { dim3 g(DLAT / 32, 2 * DLAT / 32);
      k_cvt_wt<<<g, dim3(32, 8)>>>(Wread, WrH, WrL, 2 * DLAT, DLAT); }
    { dim3 g(DSYM / 32, DLAT / 32);
      k_cvt_wt<<<g, dim3(32, 8)>>>(Wsym, WsH, WsL, DLAT, DSYM); }
    { dim3 g(DLAT / 32, (DLAT + DSYM) / 32);
      k_cvt_wt<<<g, dim3(32, 8)>>>(Wc1, W1H, W1L, DLAT + DSYM, DLAT); }

    // 1) zc[:,0:1024] = bc @ Wread^T + bread   (K=2048, N=1024)  [3-term, hi/lo out]
    k_tc<3,1,0,0,1><<<dim3(DLAT / 128, NTOK / 128), TCTHR, TC_SMEM>>>(
        bcH, bcL, 2 * DLAT, WrH, WrL, bread, nullptr,
        nullptr, zcH, zcL, DLAT + DSYM, DLAT, 2 * DLAT);

    { dim3 g(DLAT / 32, DLAT / 32);
      k_cvt_wt<<<g, dim3(32, 8)>>>(Wc2, W2H, W2L, DLAT, DLAT); }

    // 2) raw = zc[:,0:1024] @ Wsym^T + bsym    (K=1024, N=256)   [3-term, hi/lo out]
    k_tc<3,1,0,0,1><<<dim3(DSYM / 128, NTOK / 128), TCTHR, TC_SMEM>>>(
        zcH, zcL, DLAT + DSYM, WsH, WsL, bsym, nullptr,
        nullptr, rwH, rwL, DSYM, DSYM, DLAT);
    // 3) scores = raw @ cb^T                   (K=256, N=512)    [3-term, f32 out]
    k_tc<3,0,0,0,0><<<dim3(NCODE / 128, NTOK / 128), TCTHR, TC_SMEM>>>(
        rwH, rwL, DSYM, cbH, cbL, nullptr, nullptr,
        scores, nullptr, nullptr, 0, NCODE, DSYM);
    k_vq<<<(NTOK * 32 + 255) / 256, 256>>>(cb, out_quant, out_idx);
    // 4) h = relu(zc @ Wc1^T + bc1)            (K=1280, N=1024)  [2-term, hi out]
    k_tc<2,1,1,0,2><<<dim3(DLAT / 128, NTOK / 128), TCTHR, TC_SMEM>>>(
        zcH, nullptr, DLAT + DSYM, W1H, W1L, bc1, nullptr,
        nullptr, hH, nullptr, DLAT, DLAT, DLAT + DSYM);
    // 5) out = h @ Wc2^T + bc2 + token         (K=1024, N=1024)  [2-term, f32+res]
    k_tc<2,1,0,1,0><<<dim3(DLAT / 128, NTOK / 128), TCTHR, TC_SMEM>>>(
        hH, nullptr, DLAT, W2H, W2L, bc2, token,
        out_node, nullptr, nullptr, 0, DLAT, DLAT);
    k_mask<<<1, 32>>>(out_mask);
}